// round 13
// baseline (speedup 1.0000x reference)
#include <cuda_runtime.h>
#include <cstdint>
#include <cstddef>

// ---------------- problem constants ----------------
#define NA 200000      // atoms
#define NB 400000      // bonds
#define NM 10000       // molecules
#define AF 133         // atom feature dim
#define BFD 13         // bond feature dim
#define HID 300        // hidden
#define NPAD 320       // padded hidden (5 x 64 N-tiles)
#define NT 5           // N tiles of 64
#define NTASK 12
#define DEPTH 3
#define KP_I 160       // padded K for h0 init  (146 -> 160)
#define KP_H 320       // padded K for W_h      (300 -> 320)
#define KP_O 448       // padded K for W_o      (433 -> 448)

// ---------------- scratch (device globals; no allocation allowed) -------
static __device__ float g_h0 [(size_t)NB * NPAD];   // 512 MB
static __device__ float g_h  [(size_t)NB * NPAD];   // 512 MB
static __device__ float g_Y  [(size_t)NB * NPAD];   // 512 MB
static __device__ float g_am [(size_t)NA * NPAD];   // 256 MB
static __device__ float g_am2[(size_t)NA * NPAD];   // 256 MB
static __device__ float g_Ain[(size_t)NA * KP_O];   // 358 MB (packed A)
static __device__ float g_mol[(size_t)NM * NPAD];
static __device__ float g_o1 [(size_t)NM * NPAD];
static __device__ float g_WpI[(size_t)NPAD * KP_I];
static __device__ float g_WpH[(size_t)NPAD * KP_H];
static __device__ float g_WpO[(size_t)NPAD * KP_O];
static __device__ float g_WpR[(size_t)NPAD * KP_H];
static __device__ float g_bO [NPAD];
static __device__ float g_bR [NPAD];
static __device__ float g_zb [NPAD];                // stays zero
static __device__ int   g_tgt[NB];

__device__ __forceinline__ uint32_t f2tf32(float x) {
    uint32_t r; asm("cvt.rna.tf32.f32 %0, %1;" : "=r"(r) : "f"(x)); return r;
}
__device__ __forceinline__ void mma8(float* d, const uint32_t* a, const uint32_t* b) {
    asm volatile(
        "mma.sync.aligned.m16n8k8.row.col.f32.tf32.tf32.f32 "
        "{%0,%1,%2,%3}, {%4,%5,%6,%7}, {%8,%9}, {%0,%1,%2,%3};"
        : "+f"(d[0]), "+f"(d[1]), "+f"(d[2]), "+f"(d[3])
        : "r"(a[0]), "r"(a[1]), "r"(a[2]), "r"(a[3]), "r"(b[0]), "r"(b[1]));
}

// ================= tf32 mma.sync GEMM: C[M x 320] = epi(A @ Wp^T) ==========
// Wp [320 x KP] row-major. Grid (NT, ceil(M/128)), block 128.
// CTA tile 128x64, BK=32. 4 warps: 2(M) x 2(N); warp tile 64x32
// (4 m-frags x 4 n-frags, 64 acc regs). Paired-k smem permutation, stride 40:
// every fragment load is one conflict-free LDS.64; 0.75 LDS per mma.
// DOUBLE-BUFFERED smem stages: one __syncthreads per chunk; staging stores
// for chunk c+1 run behind the mma of chunk c on the other buffer.
// EPI 0: store Y (raw) + atomicAdd accb[ridx[r]*320 + c] for c<300
// EPI 1: relu(acc + biasp[c]); atomicAdd accb[ridx[r]*320 + c] for c<300
// EPI 2: relu(acc + biasp[c]); store Y
#define SA 40
static constexpr int ASZ = 128 * SA;          // u32 per A stage
static constexpr int WSZ = 64 * SA;           // u32 per W stage
static constexpr int SMEM_G = 2 * (ASZ + WSZ) * 4;  // 61440 bytes

template <int EPI>
__global__ __launch_bounds__(128, 2) void mma_gemm(
    const float* __restrict__ A, int M, int KP,
    const float* __restrict__ Wp, const float* __restrict__ biasp,
    const int* __restrict__ ridx,
    float* __restrict__ Y, float* __restrict__ accb)
{
    extern __shared__ __align__(16) uint32_t smemu[];
    uint32_t* const Asb[2] = { smemu,           smemu + ASZ };
    uint32_t* const Wsb[2] = { smemu + 2 * ASZ, smemu + 2 * ASZ + WSZ };

    const int tid  = threadIdx.x;
    const int lane = tid & 31;
    const int wid  = tid >> 5;          // 0..3
    const int warpM = wid >> 1;         // 0..1
    const int warpN = wid & 1;          // 0..1
    const int row0 = blockIdx.y * 128;
    const int col0 = blockIdx.x * 64;
    const int nchunks = KP >> 5;

    // staging: thread covers 8 consecutive k at (row, kh8); A: 4 row-passes,
    // W: 2 row-passes
    const int srow = tid >> 2;          // 0..31
    const int kh8  = (tid & 3) << 3;    // 0,8,16,24
    const float* apt[4]; bool avl[4];
#pragma unroll
    for (int p = 0; p < 4; p++) {
        int r = row0 + p * 32 + srow;
        avl[p] = r < M;
        apt[p] = A + (size_t)r * KP + kh8;
    }
    const float* wpt[2];
#pragma unroll
    for (int p = 0; p < 2; p++)
        wpt[p] = Wp + (size_t)(col0 + p * 32 + srow) * KP + kh8;

    float areg[32], wreg[16];
    auto loadA = [&](int koff) {
#pragma unroll
        for (int p = 0; p < 4; p++) {
            float4 v0, v1;
            if (avl[p]) {
                v0 = *reinterpret_cast<const float4*>(apt[p] + koff);
                v1 = *reinterpret_cast<const float4*>(apt[p] + koff + 4);
            } else {
                v0 = make_float4(0.f, 0.f, 0.f, 0.f); v1 = v0;
            }
            areg[p*8+0] = v0.x; areg[p*8+1] = v0.y;
            areg[p*8+2] = v0.z; areg[p*8+3] = v0.w;
            areg[p*8+4] = v1.x; areg[p*8+5] = v1.y;
            areg[p*8+6] = v1.z; areg[p*8+7] = v1.w;
        }
    };
    auto loadW = [&](int koff) {
#pragma unroll
        for (int p = 0; p < 2; p++) {
            float4 v0 = *reinterpret_cast<const float4*>(wpt[p] + koff);
            float4 v1 = *reinterpret_cast<const float4*>(wpt[p] + koff + 4);
            wreg[p*8+0] = v0.x; wreg[p*8+1] = v0.y;
            wreg[p*8+2] = v0.z; wreg[p*8+3] = v0.w;
            wreg[p*8+4] = v1.x; wreg[p*8+5] = v1.y;
            wreg[p*8+6] = v1.z; wreg[p*8+7] = v1.w;
        }
    };
    auto storeStage = [&](int buf) {
        uint32_t* As = Asb[buf];
        uint32_t* Ws = Wsb[buf];
#pragma unroll
        for (int p = 0; p < 4; p++) {
            uint32_t* base = &As[(p * 32 + srow) * SA + (kh8 >> 3) * 8];
#pragma unroll
            for (int w = 0; w < 4; w++) {
                uint2 q; q.x = f2tf32(areg[p*8+w]); q.y = f2tf32(areg[p*8+w+4]);
                *reinterpret_cast<uint2*>(base + 2 * w) = q;
            }
        }
#pragma unroll
        for (int p = 0; p < 2; p++) {
            uint32_t* base = &Ws[(p * 32 + srow) * SA + (kh8 >> 3) * 8];
#pragma unroll
            for (int w = 0; w < 4; w++) {
                uint2 q; q.x = f2tf32(wreg[p*8+w]); q.y = f2tf32(wreg[p*8+w+4]);
                *reinterpret_cast<uint2*>(base + 2 * w) = q;
            }
        }
    };

    float acc[4][4][4];
#pragma unroll
    for (int i = 0; i < 4; i++)
#pragma unroll
        for (int j = 0; j < 4; j++)
#pragma unroll
            for (int q = 0; q < 4; q++) acc[i][j][q] = 0.f;

    // prologue: stage chunk 0 into buffer 0
    loadA(0);
    loadW(0);
    storeStage(0);
    __syncthreads();

    for (int c = 0; c < nchunks; c++) {
        const bool more = (c + 1 < nchunks);
        // prefetch next chunk into registers (overlaps mma below)
        if (more) { loadA((c + 1) * 32); loadW((c + 1) * 32); }
        const uint32_t* As = Asb[c & 1];
        const uint32_t* Ws = Wsb[c & 1];
        // mma over 4 k-steps on current buffer
#pragma unroll
        for (int s = 0; s < 4; s++) {
            uint32_t a[4][4], b[4][2];
#pragma unroll
            for (int mf = 0; mf < 4; mf++) {
                int r = warpM * 64 + mf * 16 + (lane >> 2);
                uint2 lo = *reinterpret_cast<const uint2*>(
                    &As[r * SA + s * 8 + 2 * (lane & 3)]);
                uint2 hi = *reinterpret_cast<const uint2*>(
                    &As[(r + 8) * SA + s * 8 + 2 * (lane & 3)]);
                a[mf][0] = lo.x; a[mf][1] = hi.x; a[mf][2] = lo.y; a[mf][3] = hi.y;
            }
#pragma unroll
            for (int nf = 0; nf < 4; nf++) {
                int n = warpN * 32 + nf * 8 + (lane >> 2);
                uint2 bb = *reinterpret_cast<const uint2*>(
                    &Ws[n * SA + s * 8 + 2 * (lane & 3)]);
                b[nf][0] = bb.x; b[nf][1] = bb.y;
            }
#pragma unroll
            for (int mf = 0; mf < 4; mf++)
#pragma unroll
                for (int nf = 0; nf < 4; nf++)
                    mma8(acc[mf][nf], a[mf], b[nf]);
        }
        // stage next chunk into the other buffer (behind the mma)
        if (more) {
            storeStage((c + 1) & 1);
            __syncthreads();
        }
    }

    // ---- epilogue ----
#pragma unroll
    for (int mf = 0; mf < 4; mf++) {
        int r0 = row0 + warpM * 64 + mf * 16 + (lane >> 2);
        int r1 = r0 + 8;
        bool v0 = r0 < M, v1 = r1 < M;
        int t0 = 0, t1 = 0;
        if (EPI == 0 || EPI == 1) {
            t0 = v0 ? ridx[r0] : 0;
            t1 = v1 ? ridx[r1] : 0;
        }
#pragma unroll
        for (int nf = 0; nf < 4; nf++) {
            int col = col0 + warpN * 32 + nf * 8 + 2 * (lane & 3);
            float c0 = acc[mf][nf][0], c1 = acc[mf][nf][1];
            float c2 = acc[mf][nf][2], c3 = acc[mf][nf][3];
            if (EPI == 1 || EPI == 2) {
                float2 bsv = *reinterpret_cast<const float2*>(&biasp[col]);
                c0 = fmaxf(c0 + bsv.x, 0.f); c1 = fmaxf(c1 + bsv.y, 0.f);
                c2 = fmaxf(c2 + bsv.x, 0.f); c3 = fmaxf(c3 + bsv.y, 0.f);
            }
            if (EPI == 0 || EPI == 2) {
                if (v0) *reinterpret_cast<float2*>(Y + (size_t)r0 * NPAD + col)
                            = make_float2(c0, c1);
                if (v1) *reinterpret_cast<float2*>(Y + (size_t)r1 * NPAD + col)
                            = make_float2(c2, c3);
            }
            if (EPI == 0 || EPI == 1) {
                if (col < HID) {
                    if (v0) {
                        float* p = accb + (size_t)t0 * NPAD + col;
                        atomicAdd(p, c0); atomicAdd(p + 1, c1);
                    }
                    if (v1) {
                        float* p = accb + (size_t)t1 * NPAD + col;
                        atomicAdd(p, c2); atomicAdd(p + 1, c3);
                    }
                }
            }
        }
    }
}

// --------- target atoms: tgt[b] = b2a[b2revb[b]] ---------------------------
__global__ void tgt_kernel(const int* __restrict__ b2a,
                           const int* __restrict__ b2revb,
                           int* __restrict__ tgt)
{
    int b = blockIdx.x * blockDim.x + threadIdx.x;
    if (b < NB) tgt[b] = b2a[b2revb[b]];
}

// --------- pack A for h0 init: [NB x 160] = concat(f_atoms[b2a], f_bonds, 0)
__global__ void pack_h0A(const float* __restrict__ fa, const float* __restrict__ fb,
                         const int* __restrict__ b2a, float* __restrict__ Ain)
{
    size_t idx = (size_t)blockIdx.x * blockDim.x + threadIdx.x;
    if (idx >= (size_t)NB * KP_I) return;
    int r = (int)(idx / KP_I), k = (int)(idx % KP_I);
    float v = 0.f;
    if (k < AF)            v = fa[(size_t)b2a[r] * AF + k];
    else if (k < AF + BFD) v = fb[(size_t)r * BFD + (k - AF)];
    Ain[idx] = v;
}

// --------- pack A for readout: [NA x 448] = concat(f_atoms, amsg, 0) -------
__global__ void pack_AoA(const float* __restrict__ fa, const float* __restrict__ am,
                         float* __restrict__ Ain)
{
    size_t idx = (size_t)blockIdx.x * blockDim.x + threadIdx.x;
    if (idx >= (size_t)NA * KP_O) return;
    int a = (int)(idx / KP_O), k = (int)(idx % KP_O);
    float v = 0.f;
    if (k < AF)            v = fa[(size_t)a * AF + k];
    else if (k < AF + HID) v = am[(size_t)a * NPAD + (k - AF)];
    Ain[idx] = v;
}

// --------- zero-pad a weight [rows x cols] into [320 x KP] ----------------
__global__ void pad_W(const float* __restrict__ src, int rows, int cols, int KP,
                      float* __restrict__ dst)
{
    int idx = blockIdx.x * blockDim.x + threadIdx.x;
    if (idx >= NPAD * KP) return;
    int rp = idx / KP, k = idx % KP;
    dst[idx] = (rp < rows && k < cols) ? src[(size_t)rp * cols + k] : 0.f;
}

__global__ void pad_bias(const float* __restrict__ src, float* __restrict__ dst)
{
    int c = threadIdx.x + blockIdx.x * blockDim.x;
    if (c < NPAD) dst[c] = (c < HID) ? src[c] : 0.f;
}

// --------- combine: h[b] = relu(h0[b] + amsg[b2a[b]] - Y[b2revb[b]]) -------
// FUSE: also atomicAdd h[b] into acc2[tgt[b]] (final bond->atom aggregation)
template <bool FUSE>
__global__ void combine_kernel(const float* __restrict__ h0,
                               const float* __restrict__ amsg,
                               const float* __restrict__ Y,
                               const int* __restrict__ b2a,
                               const int* __restrict__ b2revb,
                               float* __restrict__ hout,
                               const int* __restrict__ tgt,
                               float* __restrict__ acc2)
{
    const int CH = NPAD / 4; // 80
    size_t tid = (size_t)blockIdx.x * blockDim.x + threadIdx.x;
    if (tid >= (size_t)NB * CH) return;
    int bond = (int)(tid / CH);
    int c = (int)(tid % CH);
    int a  = b2a[bond];
    int rb = b2revb[bond];
    float4 v0 = reinterpret_cast<const float4*>(h0   + (size_t)bond * NPAD)[c];
    float4 va = reinterpret_cast<const float4*>(amsg + (size_t)a    * NPAD)[c];
    float4 vy = reinterpret_cast<const float4*>(Y    + (size_t)rb   * NPAD)[c];
    float4 r;
    r.x = fmaxf(v0.x + va.x - vy.x, 0.f);
    r.y = fmaxf(v0.y + va.y - vy.y, 0.f);
    r.z = fmaxf(v0.z + va.z - vy.z, 0.f);
    r.w = fmaxf(v0.w + va.w - vy.w, 0.f);
    reinterpret_cast<float4*>(hout + (size_t)bond * NPAD)[c] = r;
    if (FUSE) {
        if (c * 4 < HID) {  // pad cols are zero; skip their atomics
            float* dst = acc2 + (size_t)tgt[bond] * NPAD + c * 4;
            atomicAdd(dst + 0, r.x);
            atomicAdd(dst + 1, r.y);
            atomicAdd(dst + 2, r.z);
            atomicAdd(dst + 3, r.w);
        }
    }
}

// --------- final logits -----------------------------------------------------
__global__ void logits_kernel(const float* __restrict__ X,
                              const float* __restrict__ W2,
                              const float* __restrict__ b2,
                              float* __restrict__ out)
{
    int warp = (blockIdx.x * blockDim.x + threadIdx.x) >> 5;
    int lane = threadIdx.x & 31;
    if (warp >= NM) return;
    const float* x = X + (size_t)warp * NPAD;
    float acc[NTASK];
#pragma unroll
    for (int t = 0; t < NTASK; t++) acc[t] = 0.f;
    for (int k = lane; k < HID; k += 32) {
        float xv = x[k];
#pragma unroll
        for (int t = 0; t < NTASK; t++)
            acc[t] = fmaf(xv, W2[t * HID + k], acc[t]);
    }
#pragma unroll
    for (int t = 0; t < NTASK; t++) {
        float v = acc[t];
#pragma unroll
        for (int off = 16; off; off >>= 1)
            v += __shfl_down_sync(0xffffffffu, v, off);
        if (lane == 0) out[warp * NTASK + t] = v + b2[t];
    }
}

// ---------------- driver ----------------
extern "C" void kernel_launch(void* const* d_in, const int* in_sizes, int n_in,
                              void* d_out, int out_size)
{
    const float* f_atoms = (const float*)d_in[0];
    const float* f_bonds = (const float*)d_in[1];
    const int*   b2a     = (const int*)d_in[2];
    const int*   b2revb  = (const int*)d_in[3];
    const int*   mol_ids = (const int*)d_in[4];
    const float* W_i     = (const float*)d_in[5];
    const float* W_h     = (const float*)d_in[6];
    const float* W_o     = (const float*)d_in[7];
    const float* b_o     = (const float*)d_in[8];
    const float* W_r1    = (const float*)d_in[9];
    const float* b_r1    = (const float*)d_in[10];
    const float* W_r2    = (const float*)d_in[11];
    const float* b_r2    = (const float*)d_in[12];
    float* out = (float*)d_out;

    float *h0, *h, *Y, *am, *am2, *Ain, *mol, *o1;
    float *WpI, *WpH, *WpO, *WpR, *bO, *bR, *zb;
    int* tgt;
    cudaGetSymbolAddress((void**)&h0,  g_h0);
    cudaGetSymbolAddress((void**)&h,   g_h);
    cudaGetSymbolAddress((void**)&Y,   g_Y);
    cudaGetSymbolAddress((void**)&am,  g_am);
    cudaGetSymbolAddress((void**)&am2, g_am2);
    cudaGetSymbolAddress((void**)&Ain, g_Ain);
    cudaGetSymbolAddress((void**)&mol, g_mol);
    cudaGetSymbolAddress((void**)&o1,  g_o1);
    cudaGetSymbolAddress((void**)&WpI, g_WpI);
    cudaGetSymbolAddress((void**)&WpH, g_WpH);
    cudaGetSymbolAddress((void**)&WpO, g_WpO);
    cudaGetSymbolAddress((void**)&WpR, g_WpR);
    cudaGetSymbolAddress((void**)&bO,  g_bO);
    cudaGetSymbolAddress((void**)&bR,  g_bR);
    cudaGetSymbolAddress((void**)&zb,  g_zb);
    cudaGetSymbolAddress((void**)&tgt, g_tgt);

    cudaFuncSetAttribute(mma_gemm<0>, cudaFuncAttributeMaxDynamicSharedMemorySize, SMEM_G);
    cudaFuncSetAttribute(mma_gemm<1>, cudaFuncAttributeMaxDynamicSharedMemorySize, SMEM_G);
    cudaFuncSetAttribute(mma_gemm<2>, cudaFuncAttributeMaxDynamicSharedMemorySize, SMEM_G);

    const dim3 blk(256);
    const dim3 gblk(128);   // GEMM uses 128 threads (4 warps)

    // 0) indices + padded weights/biases
    tgt_kernel<<<(NB + 255) / 256, blk>>>(b2a, b2revb, tgt);
    pad_W<<<(NPAD * KP_I + 255) / 256, blk>>>(W_i,  HID, AF + BFD, KP_I, WpI);
    pad_W<<<(NPAD * KP_H + 255) / 256, blk>>>(W_h,  HID, HID,      KP_H, WpH);
    pad_W<<<(NPAD * KP_O + 255) / 256, blk>>>(W_o,  HID, AF + HID, KP_O, WpO);
    pad_W<<<(NPAD * KP_H + 255) / 256, blk>>>(W_r1, HID, HID,      KP_H, WpR);
    pad_bias<<<2, 256>>>(b_o,  bO);
    pad_bias<<<2, 256>>>(b_r1, bR);

    // 1) h0 = relu(concat(f_atoms[b2a], f_bonds) @ W_i^T)   [tf32 mma.sync]
    {
        size_t n = (size_t)NB * KP_I;
        pack_h0A<<<(unsigned)((n + 255) / 256), blk>>>(f_atoms, f_bonds, b2a, Ain);
        dim3 g(NT, NB / 128);
        mma_gemm<2><<<g, gblk, SMEM_G>>>(Ain, NB, KP_I, WpI, zb, nullptr, h0, nullptr);
    }

    // 2) DEPTH message rounds. Linear commutes with segment_sum:
    //    Y = h @ W_h^T (epilogue scatters Y into am by tgt);
    //    h' = relu(h0 + am[b2a] - Y[b2revb])  (round 3 also scatters h' -> am2)
    const unsigned combB = (unsigned)(((size_t)NB * (NPAD / 4) + 255) / 256);
    float* h_cur = h0;
    for (int d = 0; d < DEPTH; d++) {
        cudaMemsetAsync(am, 0, (size_t)NA * NPAD * sizeof(float));
        dim3 g(NT, NB / 128);
        mma_gemm<0><<<g, gblk, SMEM_G>>>(h_cur, NB, KP_H, WpH, nullptr, tgt, Y, am);
        if (d < DEPTH - 1) {
            combine_kernel<false><<<combB, blk>>>(h0, am, Y, b2a, b2revb, h,
                                                  nullptr, nullptr);
        } else {
            cudaMemsetAsync(am2, 0, (size_t)NA * NPAD * sizeof(float));
            combine_kernel<true><<<combB, blk>>>(h0, am, Y, b2a, b2revb, h,
                                                 tgt, am2);
        }
        h_cur = h;
    }

    // 3) atom readout fused with molecule pooling:
    //    mol += relu(concat(f_atoms, am2) @ W_o^T + b_o) scattered by mol_ids
    {
        size_t n = (size_t)NA * KP_O;
        pack_AoA<<<(unsigned)((n + 255) / 256), blk>>>(f_atoms, am2, Ain);
        cudaMemsetAsync(mol, 0, (size_t)NM * NPAD * sizeof(float));
        dim3 g(NT, (NA + 127) / 128);
        mma_gemm<1><<<g, gblk, SMEM_G>>>(Ain, NA, KP_O, WpO, bO, mol_ids, nullptr, mol);
    }

    // 4) readout head
    {
        dim3 g(NT, (NM + 127) / 128);
        mma_gemm<2><<<g, gblk, SMEM_G>>>(mol, NM, KP_H, WpR, bR, nullptr, o1, nullptr);
    }
    logits_kernel<<<(NM * 32 + 255) / 256, blk>>>(o1, W_r2, b_r2, out);
}

// round 14
// speedup vs baseline: 1.3561x; 1.3561x over previous
#include <cuda_runtime.h>
#include <cstdint>
#include <cstddef>

// ---------------- problem constants ----------------
#define NA 200000      // atoms
#define NB 400000      // bonds
#define NM 10000       // molecules
#define AF 133         // atom feature dim
#define BFD 13         // bond feature dim
#define HID 300        // hidden
#define NPAD 320       // padded hidden (5 x 64 N-tiles)
#define NT 5           // N tiles of 64
#define NTASK 12
#define DEPTH 3
#define KP_I 160       // padded K for h0 init  (146 -> 160)
#define KP_H 320       // padded K for W_h      (300 -> 320)
#define KP_O 448       // padded K for W_o      (433 -> 448)
#define CAP 64         // bond-bucket capacity per atom

// ---------------- scratch (device globals; no allocation allowed) -------
static __device__ float g_h0 [(size_t)NB * NPAD];   // 512 MB
static __device__ float g_h  [(size_t)NB * NPAD];   // 512 MB
static __device__ float g_Y  [(size_t)NB * NPAD];   // 512 MB
static __device__ float g_am [(size_t)NA * NPAD];   // 256 MB
static __device__ float g_am2[(size_t)NA * NPAD];   // 256 MB
static __device__ float g_Ain[(size_t)NA * KP_O];   // 358 MB (packed A)
static __device__ float g_mol[(size_t)NM * NPAD];
static __device__ float g_o1 [(size_t)NM * NPAD];
static __device__ float g_WpI[(size_t)NPAD * KP_I];
static __device__ float g_WpH[(size_t)NPAD * KP_H];
static __device__ float g_WpO[(size_t)NPAD * KP_O];
static __device__ float g_WpR[(size_t)NPAD * KP_H];
static __device__ float g_bO [NPAD];
static __device__ float g_bR [NPAD];
static __device__ float g_zb [NPAD];                // stays zero
static __device__ int   g_tgt[NB];
static __device__ int   g_cnt[NA];
static __device__ int   g_bkt[(size_t)NA * CAP];    // 51 MB

__device__ __forceinline__ uint32_t f2tf32(float x) {
    uint32_t r; asm("cvt.rna.tf32.f32 %0, %1;" : "=r"(r) : "f"(x)); return r;
}
__device__ __forceinline__ void mma8(float* d, const uint32_t* a, const uint32_t* b) {
    asm volatile(
        "mma.sync.aligned.m16n8k8.row.col.f32.tf32.tf32.f32 "
        "{%0,%1,%2,%3}, {%4,%5,%6,%7}, {%8,%9}, {%0,%1,%2,%3};"
        : "+f"(d[0]), "+f"(d[1]), "+f"(d[2]), "+f"(d[3])
        : "r"(a[0]), "r"(a[1]), "r"(a[2]), "r"(a[3]), "r"(b[0]), "r"(b[1]));
}

// ================= tf32 mma.sync GEMM: C[M x 320] = epi(A @ Wp^T) ==========
// Wp [320 x KP] row-major. Grid (NT, ceil(M/128)), block 128.
// CTA tile 128x64, BK=32. 4 warps: 2(M) x 2(N); warp tile 64x32
// (4 m-frags x 4 n-frags, 64 acc regs). Paired-k smem permutation, stride 40:
// every fragment load is one conflict-free LDS.64; 0.75 LDS per mma.
// SINGLE-buffered (measured best: register lifetimes stay short).
// EPI 0: store Y (raw), no atomics
// EPI 1: relu(acc + biasp[c]); atomicAdd accb[ridx[r]*320 + c] for c<300
// EPI 2: relu(acc + biasp[c]); store Y
#define SA 40
template <int EPI>
__global__ __launch_bounds__(128, 2) void mma_gemm(
    const float* __restrict__ A, int M, int KP,
    const float* __restrict__ Wp, const float* __restrict__ biasp,
    const int* __restrict__ ridx,
    float* __restrict__ Y, float* __restrict__ accb)
{
    __shared__ __align__(16) uint32_t As[128 * SA];
    __shared__ __align__(16) uint32_t Ws[64 * SA];

    const int tid  = threadIdx.x;
    const int lane = tid & 31;
    const int wid  = tid >> 5;          // 0..3
    const int warpM = wid >> 1;         // 0..1
    const int warpN = wid & 1;          // 0..1
    const int row0 = blockIdx.y * 128;
    const int col0 = blockIdx.x * 64;
    const int nchunks = KP >> 5;

    // staging: thread covers 8 consecutive k at (row, kh8); A: 4 row-passes,
    // W: 2 row-passes
    const int srow = tid >> 2;          // 0..31
    const int kh8  = (tid & 3) << 3;    // 0,8,16,24
    const float* apt[4]; bool avl[4];
#pragma unroll
    for (int p = 0; p < 4; p++) {
        int r = row0 + p * 32 + srow;
        avl[p] = r < M;
        apt[p] = A + (size_t)r * KP + kh8;
    }
    const float* wpt[2];
#pragma unroll
    for (int p = 0; p < 2; p++)
        wpt[p] = Wp + (size_t)(col0 + p * 32 + srow) * KP + kh8;

    float areg[32], wreg[16];
    auto loadA = [&](int koff) {
#pragma unroll
        for (int p = 0; p < 4; p++) {
            float4 v0, v1;
            if (avl[p]) {
                v0 = *reinterpret_cast<const float4*>(apt[p] + koff);
                v1 = *reinterpret_cast<const float4*>(apt[p] + koff + 4);
            } else {
                v0 = make_float4(0.f, 0.f, 0.f, 0.f); v1 = v0;
            }
            areg[p*8+0] = v0.x; areg[p*8+1] = v0.y;
            areg[p*8+2] = v0.z; areg[p*8+3] = v0.w;
            areg[p*8+4] = v1.x; areg[p*8+5] = v1.y;
            areg[p*8+6] = v1.z; areg[p*8+7] = v1.w;
        }
    };
    auto loadW = [&](int koff) {
#pragma unroll
        for (int p = 0; p < 2; p++) {
            float4 v0 = *reinterpret_cast<const float4*>(wpt[p] + koff);
            float4 v1 = *reinterpret_cast<const float4*>(wpt[p] + koff + 4);
            wreg[p*8+0] = v0.x; wreg[p*8+1] = v0.y;
            wreg[p*8+2] = v0.z; wreg[p*8+3] = v0.w;
            wreg[p*8+4] = v1.x; wreg[p*8+5] = v1.y;
            wreg[p*8+6] = v1.z; wreg[p*8+7] = v1.w;
        }
    };

    loadA(0);
    loadW(0);

    float acc[4][4][4];
#pragma unroll
    for (int i = 0; i < 4; i++)
#pragma unroll
        for (int j = 0; j < 4; j++)
#pragma unroll
            for (int q = 0; q < 4; q++) acc[i][j][q] = 0.f;

    for (int c = 0; c < nchunks; c++) {
        // ---- store stage (convert + paired-k permute) ----
#pragma unroll
        for (int p = 0; p < 4; p++) {
            uint32_t* base = &As[(p * 32 + srow) * SA + (kh8 >> 3) * 8];
#pragma unroll
            for (int w = 0; w < 4; w++) {
                uint2 q; q.x = f2tf32(areg[p*8+w]); q.y = f2tf32(areg[p*8+w+4]);
                *reinterpret_cast<uint2*>(base + 2 * w) = q;
            }
        }
#pragma unroll
        for (int p = 0; p < 2; p++) {
            uint32_t* base = &Ws[(p * 32 + srow) * SA + (kh8 >> 3) * 8];
#pragma unroll
            for (int w = 0; w < 4; w++) {
                uint2 q; q.x = f2tf32(wreg[p*8+w]); q.y = f2tf32(wreg[p*8+w+4]);
                *reinterpret_cast<uint2*>(base + 2 * w) = q;
            }
        }
        __syncthreads();
        // ---- prefetch next chunk into registers ----
        if (c + 1 < nchunks) {
            loadA((c + 1) * 32);
            loadW((c + 1) * 32);
        }
        // ---- mma over 4 k-steps ----
#pragma unroll
        for (int s = 0; s < 4; s++) {
            uint32_t a[4][4], b[4][2];
#pragma unroll
            for (int mf = 0; mf < 4; mf++) {
                int r = warpM * 64 + mf * 16 + (lane >> 2);
                uint2 lo = *reinterpret_cast<const uint2*>(
                    &As[r * SA + s * 8 + 2 * (lane & 3)]);
                uint2 hi = *reinterpret_cast<const uint2*>(
                    &As[(r + 8) * SA + s * 8 + 2 * (lane & 3)]);
                a[mf][0] = lo.x; a[mf][1] = hi.x; a[mf][2] = lo.y; a[mf][3] = hi.y;
            }
#pragma unroll
            for (int nf = 0; nf < 4; nf++) {
                int n = warpN * 32 + nf * 8 + (lane >> 2);
                uint2 bb = *reinterpret_cast<const uint2*>(
                    &Ws[n * SA + s * 8 + 2 * (lane & 3)]);
                b[nf][0] = bb.x; b[nf][1] = bb.y;
            }
#pragma unroll
            for (int mf = 0; mf < 4; mf++)
#pragma unroll
                for (int nf = 0; nf < 4; nf++)
                    mma8(acc[mf][nf], a[mf], b[nf]);
        }
        __syncthreads();
    }

    // ---- epilogue ----
#pragma unroll
    for (int mf = 0; mf < 4; mf++) {
        int r0 = row0 + warpM * 64 + mf * 16 + (lane >> 2);
        int r1 = r0 + 8;
        bool v0 = r0 < M, v1 = r1 < M;
        int t0 = 0, t1 = 0;
        if (EPI == 1) {
            t0 = v0 ? ridx[r0] : 0;
            t1 = v1 ? ridx[r1] : 0;
        }
#pragma unroll
        for (int nf = 0; nf < 4; nf++) {
            int col = col0 + warpN * 32 + nf * 8 + 2 * (lane & 3);
            float c0 = acc[mf][nf][0], c1 = acc[mf][nf][1];
            float c2 = acc[mf][nf][2], c3 = acc[mf][nf][3];
            if (EPI == 1 || EPI == 2) {
                float2 bsv = *reinterpret_cast<const float2*>(&biasp[col]);
                c0 = fmaxf(c0 + bsv.x, 0.f); c1 = fmaxf(c1 + bsv.y, 0.f);
                c2 = fmaxf(c2 + bsv.x, 0.f); c3 = fmaxf(c3 + bsv.y, 0.f);
            }
            if (EPI == 0 || EPI == 2) {
                if (v0) *reinterpret_cast<float2*>(Y + (size_t)r0 * NPAD + col)
                            = make_float2(c0, c1);
                if (v1) *reinterpret_cast<float2*>(Y + (size_t)r1 * NPAD + col)
                            = make_float2(c2, c3);
            }
            if (EPI == 1) {
                if (col < HID) {
                    if (v0) {
                        float* p = accb + (size_t)t0 * NPAD + col;
                        atomicAdd(p, c0); atomicAdd(p + 1, c1);
                    }
                    if (v1) {
                        float* p = accb + (size_t)t1 * NPAD + col;
                        atomicAdd(p, c2); atomicAdd(p + 1, c3);
                    }
                }
            }
        }
    }
}

// --------- index prep -------------------------------------------------------
__global__ void tgt_kernel(const int* __restrict__ b2a,
                           const int* __restrict__ b2revb,
                           int* __restrict__ tgt)
{
    int b = blockIdx.x * blockDim.x + threadIdx.x;
    if (b < NB) tgt[b] = b2a[b2revb[b]];
}

__global__ void bucket_kernel(const int* __restrict__ tgt,
                              int* __restrict__ cnt, int* __restrict__ bkt)
{
    int b = blockIdx.x * blockDim.x + threadIdx.x;
    if (b >= NB) return;
    int a = tgt[b];
    int s = atomicAdd(&cnt[a], 1);
    if (s < CAP) bkt[(size_t)a * CAP + s] = b;
}

// --------- gather: out[a] = sum over bucketed bonds of X[b] ----------------
// Thread (a, c): c-th float4 chunk. Warp covers 32 consecutive chunks of the
// same/adjacent atoms -> bond-row reads are 512B-coalesced per list entry.
__global__ void gather_kernel(const float* __restrict__ X,
                              const int* __restrict__ cnt,
                              const int* __restrict__ bkt,
                              float* __restrict__ out)
{
    const int CH = NPAD / 4; // 80
    int idx = blockIdx.x * blockDim.x + threadIdx.x;
    if (idx >= NA * CH) return;
    int a = idx / CH, c = idx % CH;
    int n = cnt[a]; if (n > CAP) n = CAP;
    const int* bl = bkt + (size_t)a * CAP;
    float4 s = make_float4(0.f, 0.f, 0.f, 0.f);
    for (int j = 0; j < n; j++) {
        float4 v = reinterpret_cast<const float4*>(X + (size_t)bl[j] * NPAD)[c];
        s.x += v.x; s.y += v.y; s.z += v.z; s.w += v.w;
    }
    reinterpret_cast<float4*>(out + (size_t)a * NPAD)[c] = s;
}

// --------- pack A for h0 init: [NB x 160] = concat(f_atoms[b2a], f_bonds, 0)
__global__ void pack_h0A(const float* __restrict__ fa, const float* __restrict__ fb,
                         const int* __restrict__ b2a, float* __restrict__ Ain)
{
    size_t idx = (size_t)blockIdx.x * blockDim.x + threadIdx.x;
    if (idx >= (size_t)NB * KP_I) return;
    int r = (int)(idx / KP_I), k = (int)(idx % KP_I);
    float v = 0.f;
    if (k < AF)            v = fa[(size_t)b2a[r] * AF + k];
    else if (k < AF + BFD) v = fb[(size_t)r * BFD + (k - AF)];
    Ain[idx] = v;
}

// --------- pack A for readout: [NA x 448] = concat(f_atoms, amsg, 0) -------
__global__ void pack_AoA(const float* __restrict__ fa, const float* __restrict__ am,
                         float* __restrict__ Ain)
{
    size_t idx = (size_t)blockIdx.x * blockDim.x + threadIdx.x;
    if (idx >= (size_t)NA * KP_O) return;
    int a = (int)(idx / KP_O), k = (int)(idx % KP_O);
    float v = 0.f;
    if (k < AF)            v = fa[(size_t)a * AF + k];
    else if (k < AF + HID) v = am[(size_t)a * NPAD + (k - AF)];
    Ain[idx] = v;
}

// --------- zero-pad a weight [rows x cols] into [320 x KP] ----------------
__global__ void pad_W(const float* __restrict__ src, int rows, int cols, int KP,
                      float* __restrict__ dst)
{
    int idx = blockIdx.x * blockDim.x + threadIdx.x;
    if (idx >= NPAD * KP) return;
    int rp = idx / KP, k = idx % KP;
    dst[idx] = (rp < rows && k < cols) ? src[(size_t)rp * cols + k] : 0.f;
}

__global__ void pad_bias(const float* __restrict__ src, float* __restrict__ dst)
{
    int c = threadIdx.x + blockIdx.x * blockDim.x;
    if (c < NPAD) dst[c] = (c < HID) ? src[c] : 0.f;
}

// --------- combine: h[b] = relu(h0[b] + amsg[b2a[b]] - Y[b2revb[b]]) -------
__global__ void combine_kernel(const float* __restrict__ h0,
                               const float* __restrict__ amsg,
                               const float* __restrict__ Y,
                               const int* __restrict__ b2a,
                               const int* __restrict__ b2revb,
                               float* __restrict__ hout)
{
    const int CH = NPAD / 4; // 80
    size_t tid = (size_t)blockIdx.x * blockDim.x + threadIdx.x;
    if (tid >= (size_t)NB * CH) return;
    int bond = (int)(tid / CH);
    int c = (int)(tid % CH);
    int a  = b2a[bond];
    int rb = b2revb[bond];
    float4 v0 = reinterpret_cast<const float4*>(h0   + (size_t)bond * NPAD)[c];
    float4 va = reinterpret_cast<const float4*>(amsg + (size_t)a    * NPAD)[c];
    float4 vy = reinterpret_cast<const float4*>(Y    + (size_t)rb   * NPAD)[c];
    float4 r;
    r.x = fmaxf(v0.x + va.x - vy.x, 0.f);
    r.y = fmaxf(v0.y + va.y - vy.y, 0.f);
    r.z = fmaxf(v0.z + va.z - vy.z, 0.f);
    r.w = fmaxf(v0.w + va.w - vy.w, 0.f);
    reinterpret_cast<float4*>(hout + (size_t)bond * NPAD)[c] = r;
}

// --------- final logits -----------------------------------------------------
__global__ void logits_kernel(const float* __restrict__ X,
                              const float* __restrict__ W2,
                              const float* __restrict__ b2,
                              float* __restrict__ out)
{
    int warp = (blockIdx.x * blockDim.x + threadIdx.x) >> 5;
    int lane = threadIdx.x & 31;
    if (warp >= NM) return;
    const float* x = X + (size_t)warp * NPAD;
    float acc[NTASK];
#pragma unroll
    for (int t = 0; t < NTASK; t++) acc[t] = 0.f;
    for (int k = lane; k < HID; k += 32) {
        float xv = x[k];
#pragma unroll
        for (int t = 0; t < NTASK; t++)
            acc[t] = fmaf(xv, W2[t * HID + k], acc[t]);
    }
#pragma unroll
    for (int t = 0; t < NTASK; t++) {
        float v = acc[t];
#pragma unroll
        for (int off = 16; off; off >>= 1)
            v += __shfl_down_sync(0xffffffffu, v, off);
        if (lane == 0) out[warp * NTASK + t] = v + b2[t];
    }
}

// ---------------- driver ----------------
extern "C" void kernel_launch(void* const* d_in, const int* in_sizes, int n_in,
                              void* d_out, int out_size)
{
    const float* f_atoms = (const float*)d_in[0];
    const float* f_bonds = (const float*)d_in[1];
    const int*   b2a     = (const int*)d_in[2];
    const int*   b2revb  = (const int*)d_in[3];
    const int*   mol_ids = (const int*)d_in[4];
    const float* W_i     = (const float*)d_in[5];
    const float* W_h     = (const float*)d_in[6];
    const float* W_o     = (const float*)d_in[7];
    const float* b_o     = (const float*)d_in[8];
    const float* W_r1    = (const float*)d_in[9];
    const float* b_r1    = (const float*)d_in[10];
    const float* W_r2    = (const float*)d_in[11];
    const float* b_r2    = (const float*)d_in[12];
    float* out = (float*)d_out;

    float *h0, *h, *Y, *am, *am2, *Ain, *mol, *o1;
    float *WpI, *WpH, *WpO, *WpR, *bO, *bR, *zb;
    int *tgt, *cnt, *bkt;
    cudaGetSymbolAddress((void**)&h0,  g_h0);
    cudaGetSymbolAddress((void**)&h,   g_h);
    cudaGetSymbolAddress((void**)&Y,   g_Y);
    cudaGetSymbolAddress((void**)&am,  g_am);
    cudaGetSymbolAddress((void**)&am2, g_am2);
    cudaGetSymbolAddress((void**)&Ain, g_Ain);
    cudaGetSymbolAddress((void**)&mol, g_mol);
    cudaGetSymbolAddress((void**)&o1,  g_o1);
    cudaGetSymbolAddress((void**)&WpI, g_WpI);
    cudaGetSymbolAddress((void**)&WpH, g_WpH);
    cudaGetSymbolAddress((void**)&WpO, g_WpO);
    cudaGetSymbolAddress((void**)&WpR, g_WpR);
    cudaGetSymbolAddress((void**)&bO,  g_bO);
    cudaGetSymbolAddress((void**)&bR,  g_bR);
    cudaGetSymbolAddress((void**)&zb,  g_zb);
    cudaGetSymbolAddress((void**)&tgt, g_tgt);
    cudaGetSymbolAddress((void**)&cnt, g_cnt);
    cudaGetSymbolAddress((void**)&bkt, g_bkt);

    const dim3 blk(256);
    const dim3 gblk(128);   // GEMM uses 128 threads (4 warps)

    // 0) indices + bucket-CSR + padded weights/biases
    tgt_kernel<<<(NB + 255) / 256, blk>>>(b2a, b2revb, tgt);
    cudaMemsetAsync(cnt, 0, NA * sizeof(int));
    bucket_kernel<<<(NB + 255) / 256, blk>>>(tgt, cnt, bkt);
    pad_W<<<(NPAD * KP_I + 255) / 256, blk>>>(W_i,  HID, AF + BFD, KP_I, WpI);
    pad_W<<<(NPAD * KP_H + 255) / 256, blk>>>(W_h,  HID, HID,      KP_H, WpH);
    pad_W<<<(NPAD * KP_O + 255) / 256, blk>>>(W_o,  HID, AF + HID, KP_O, WpO);
    pad_W<<<(NPAD * KP_H + 255) / 256, blk>>>(W_r1, HID, HID,      KP_H, WpR);
    pad_bias<<<2, 256>>>(b_o,  bO);
    pad_bias<<<2, 256>>>(b_r1, bR);

    // 1) h0 = relu(concat(f_atoms[b2a], f_bonds) @ W_i^T)   [tf32 mma.sync]
    {
        size_t n = (size_t)NB * KP_I;
        pack_h0A<<<(unsigned)((n + 255) / 256), blk>>>(f_atoms, f_bonds, b2a, Ain);
        dim3 g(NT, NB / 128);
        mma_gemm<2><<<g, gblk>>>(Ain, NB, KP_I, WpI, zb, nullptr, h0, nullptr);
    }

    // 2) DEPTH message rounds. Linear commutes with segment_sum:
    //    Y = h @ W_h^T (plain store);  am = bucket-gather(Y, tgt);
    //    h' = relu(h0 + am[b2a] - Y[b2revb])
    const unsigned combB = (unsigned)(((size_t)NB * (NPAD / 4) + 255) / 256);
    const unsigned gatB  = (unsigned)((NA * (NPAD / 4) + 255) / 256);
    float* h_cur = h0;
    for (int d = 0; d < DEPTH; d++) {
        dim3 g(NT, NB / 128);
        mma_gemm<0><<<g, gblk>>>(h_cur, NB, KP_H, WpH, nullptr, nullptr, Y, nullptr);
        gather_kernel<<<gatB, blk>>>(Y, cnt, bkt, am);
        combine_kernel<<<combB, blk>>>(h0, am, Y, b2a, b2revb, h);
        h_cur = h;
    }

    // 3) final bond->atom aggregation of h via the same buckets
    gather_kernel<<<gatB, blk>>>(h_cur, cnt, bkt, am2);

    // 4) atom readout fused with molecule pooling:
    //    mol += relu(concat(f_atoms, am2) @ W_o^T + b_o) scattered by mol_ids
    {
        size_t n = (size_t)NA * KP_O;
        pack_AoA<<<(unsigned)((n + 255) / 256), blk>>>(f_atoms, am2, Ain);
        cudaMemsetAsync(mol, 0, (size_t)NM * NPAD * sizeof(float));
        dim3 g(NT, (NA + 127) / 128);
        mma_gemm<1><<<g, gblk>>>(Ain, NA, KP_O, WpO, bO, mol_ids, nullptr, mol);
    }

    // 5) readout head
    {
        dim3 g(NT, (NM + 127) / 128);
        mma_gemm<2><<<g, gblk>>>(mol, NM, KP_H, WpR, bR, nullptr, o1, nullptr);
    }
    logits_kernel<<<(NM * 32 + 255) / 256, blk>>>(o1, W_r2, b_r2, out);
}

// round 15
// speedup vs baseline: 1.4803x; 1.0916x over previous
#include <cuda_runtime.h>
#include <cstdint>
#include <cstddef>

// ---------------- problem constants ----------------
#define NA 200000      // atoms
#define NB 400000      // bonds
#define NM 10000       // molecules
#define AF 133         // atom feature dim
#define BFD 13         // bond feature dim
#define HID 300        // hidden
#define NPAD 320       // padded hidden (5 x 64 N-tiles)
#define NT 5           // N tiles of 64
#define NTASK 12
#define DEPTH 3
#define KP_I 160       // padded K for h0 init  (146 -> 160)
#define KP_H 320       // padded K for W_h      (300 -> 320)
#define KP_O 448       // padded K for W_o      (433 -> 448)
#define CAP 64         // bond-bucket capacity per atom

// All hidden-space buffers are stored in PERMUTED column order:
// within each group of 8 columns, natural k sits at pos = 2*(k&3)+((k>>2)&1).
// This matches the mma.sync tf32 fragment pairing (k, k+4), so the GEMM can
// cp.async raw 16B chunks straight into its smem layout.
// All GEMM-A/B-feeding values are pre-rounded to tf32 (cvt.rna) by producers.

// ---------------- scratch (device globals; no allocation allowed) -------
static __device__ float g_h0 [(size_t)NB * NPAD];   // 512 MB
static __device__ float g_h  [(size_t)NB * NPAD];   // 512 MB
static __device__ float g_Y  [(size_t)NB * NPAD];   // 512 MB
static __device__ float g_am [(size_t)NA * NPAD];   // 256 MB
static __device__ float g_am2[(size_t)NA * NPAD];   // 256 MB
static __device__ float g_Ain[(size_t)NA * KP_O];   // 358 MB (packed A)
static __device__ float g_mol[(size_t)NM * NPAD];
static __device__ float g_o1 [(size_t)NM * NPAD];
static __device__ float g_WpI[(size_t)NPAD * KP_I];
static __device__ float g_WpH[(size_t)NPAD * KP_H];
static __device__ float g_WpO[(size_t)NPAD * KP_O];
static __device__ float g_WpR[(size_t)NPAD * KP_H];
static __device__ float g_bO [NPAD];
static __device__ float g_bR [NPAD];
static __device__ float g_zb [NPAD];                // stays zero
static __device__ int   g_tgt[NB];
static __device__ int   g_cnt[NA];
static __device__ int   g_bkt[(size_t)NA * CAP];    // 51 MB

__device__ __forceinline__ float rndtf(float x) {
    uint32_t r; asm("cvt.rna.tf32.f32 %0, %1;" : "=r"(r) : "f"(x));
    return __uint_as_float(r);
}
__device__ __forceinline__ int permcol(int k) {
    return (k & ~7) | (((k & 3) << 1) | ((k >> 2) & 1));
}
__device__ __forceinline__ int invperm(int p) {
    return (p & ~7) | ((p >> 1) & 3) | (((p & 1) << 2));
}
__device__ __forceinline__ void mma8(float* d, const uint32_t* a, const uint32_t* b) {
    asm volatile(
        "mma.sync.aligned.m16n8k8.row.col.f32.tf32.tf32.f32 "
        "{%0,%1,%2,%3}, {%4,%5,%6,%7}, {%8,%9}, {%0,%1,%2,%3};"
        : "+f"(d[0]), "+f"(d[1]), "+f"(d[2]), "+f"(d[3])
        : "r"(a[0]), "r"(a[1]), "r"(a[2]), "r"(a[3]), "r"(b[0]), "r"(b[1]));
}

// ================= tf32 mma.sync GEMM, cp.async 3-stage pipeline ===========
// C[M x 320] = epi(A @ Wp^T).  A [M x KP] and Wp [320 x KP] are PERMUTED
// k-order and tf32-pre-rounded in gmem; staging is raw cp.async 16B chunks.
// Grid (NT, ceil(M/128)), block 128. CTA 128x64, BK=32; 4 warps 2(M)x2(N),
// warp tile 64x32 (64 acc regs). SA=40 row stride, conflict-free LDS.64.
// EPI 0: store Y (rounded) at permuted cols
// EPI 1: relu(acc+bias); atomicAdd accb[ridx[r]*320 + permcol(col)], col<300
// EPI 2: relu(acc+bias); store Y (rounded) at permuted cols
#define SA 40
static constexpr int ASZ = 128 * SA;
static constexpr int WSZ = 64 * SA;
static constexpr int STG = 3;
static constexpr int SMEM_G = STG * (ASZ + WSZ) * 4;  // 92160 bytes

template <int EPI>
__global__ __launch_bounds__(128, 2) void mma_gemm(
    const float* __restrict__ A, int M, int KP,
    const float* __restrict__ Wp, const float* __restrict__ biasp,
    const int* __restrict__ ridx,
    float* __restrict__ Y, float* __restrict__ accb)
{
    extern __shared__ __align__(16) uint32_t smemu[];

    const int tid  = threadIdx.x;
    const int lane = tid & 31;
    const int wid  = tid >> 5;          // 0..3
    const int warpM = wid >> 1;         // 0..1
    const int warpN = wid & 1;          // 0..1
    const int row0 = blockIdx.y * 128;
    const int col0 = blockIdx.x * 64;
    const int n    = KP >> 5;           // chunks

    // ---- async staging of one 32-k chunk into stage buffer ----
    auto issue = [&](int c, int buf) {
        uint32_t* As = smemu + buf * ASZ;
        uint32_t* Ws = smemu + STG * ASZ + buf * WSZ;
        const int koff = c * 32;
#pragma unroll
        for (int t = 0; t < 8; t++) {           // A: 128 rows x 8 x 16B
            int j = tid + t * 128;
            int row = j >> 3, q = j & 7;
            int rg = row0 + row;
            bool v = rg < M;
            const float* src = A + (size_t)(v ? rg : 0) * KP + koff + q * 4;
            uint32_t d = (uint32_t)__cvta_generic_to_shared(&As[row * SA + q * 4]);
            int sz = v ? 16 : 0;
            asm volatile("cp.async.cg.shared.global [%0], [%1], 16, %2;"
                         :: "r"(d), "l"(src), "r"(sz));
        }
#pragma unroll
        for (int t = 0; t < 4; t++) {           // W: 64 rows x 8 x 16B
            int j = tid + t * 128;
            int row = j >> 3, q = j & 7;
            const float* src = Wp + (size_t)(col0 + row) * KP + koff + q * 4;
            uint32_t d = (uint32_t)__cvta_generic_to_shared(&Ws[row * SA + q * 4]);
            asm volatile("cp.async.cg.shared.global [%0], [%1], 16, 16;"
                         :: "r"(d), "l"(src));
        }
        asm volatile("cp.async.commit_group;");
    };

    float acc[4][4][4];
#pragma unroll
    for (int i = 0; i < 4; i++)
#pragma unroll
        for (int j = 0; j < 4; j++)
#pragma unroll
            for (int q = 0; q < 4; q++) acc[i][j][q] = 0.f;

    issue(0, 0);
    if (n > 1) issue(1, 1);

    for (int c = 0; c < n; c++) {
        if (c + 1 < n) { asm volatile("cp.async.wait_group 1;"); }
        else           { asm volatile("cp.async.wait_group 0;"); }
        __syncthreads();                       // chunk c visible; prior mma done
        if (c + 2 < n) issue(c + 2, (c + 2) % STG);

        const uint32_t* As = smemu + (c % STG) * ASZ;
        const uint32_t* Ws = smemu + STG * ASZ + (c % STG) * WSZ;
#pragma unroll
        for (int s = 0; s < 4; s++) {
            uint32_t a[4][4], b[4][2];
#pragma unroll
            for (int mf = 0; mf < 4; mf++) {
                int r = warpM * 64 + mf * 16 + (lane >> 2);
                uint2 lo = *reinterpret_cast<const uint2*>(
                    &As[r * SA + s * 8 + 2 * (lane & 3)]);
                uint2 hi = *reinterpret_cast<const uint2*>(
                    &As[(r + 8) * SA + s * 8 + 2 * (lane & 3)]);
                a[mf][0] = lo.x; a[mf][1] = hi.x; a[mf][2] = lo.y; a[mf][3] = hi.y;
            }
#pragma unroll
            for (int nf = 0; nf < 4; nf++) {
                int nn = warpN * 32 + nf * 8 + (lane >> 2);
                uint2 bb = *reinterpret_cast<const uint2*>(
                    &Ws[nn * SA + s * 8 + 2 * (lane & 3)]);
                b[nf][0] = bb.x; b[nf][1] = bb.y;
            }
#pragma unroll
            for (int mf = 0; mf < 4; mf++)
#pragma unroll
                for (int nf = 0; nf < 4; nf++)
                    mma8(acc[mf][nf], a[mf], b[nf]);
        }
    }

    // ---- epilogue (stores at permuted column positions) ----
#pragma unroll
    for (int mf = 0; mf < 4; mf++) {
        int r0 = row0 + warpM * 64 + mf * 16 + (lane >> 2);
        int r1 = r0 + 8;
        bool v0 = r0 < M, v1 = r1 < M;
        int t0 = 0, t1 = 0;
        if (EPI == 1) {
            t0 = v0 ? ridx[r0] : 0;
            t1 = v1 ? ridx[r1] : 0;
        }
#pragma unroll
        for (int nf = 0; nf < 4; nf++) {
            int col = col0 + warpN * 32 + nf * 8 + 2 * (lane & 3);
            int pc0 = permcol(col), pc1 = permcol(col + 1);
            float c0 = acc[mf][nf][0], c1 = acc[mf][nf][1];
            float c2 = acc[mf][nf][2], c3 = acc[mf][nf][3];
            if (EPI == 1 || EPI == 2) {
                float2 bsv = *reinterpret_cast<const float2*>(&biasp[col]);
                c0 = fmaxf(c0 + bsv.x, 0.f); c1 = fmaxf(c1 + bsv.y, 0.f);
                c2 = fmaxf(c2 + bsv.x, 0.f); c3 = fmaxf(c3 + bsv.y, 0.f);
            }
            if (EPI == 0 || EPI == 2) {
                if (v0) {
                    Y[(size_t)r0 * NPAD + pc0] = rndtf(c0);
                    Y[(size_t)r0 * NPAD + pc1] = rndtf(c1);
                }
                if (v1) {
                    Y[(size_t)r1 * NPAD + pc0] = rndtf(c2);
                    Y[(size_t)r1 * NPAD + pc1] = rndtf(c3);
                }
            }
            if (EPI == 1) {
                if (col < HID) {
                    if (v0) {
                        atomicAdd(accb + (size_t)t0 * NPAD + pc0, c0);
                        atomicAdd(accb + (size_t)t0 * NPAD + pc1, c1);
                    }
                    if (v1) {
                        atomicAdd(accb + (size_t)t1 * NPAD + pc0, c2);
                        atomicAdd(accb + (size_t)t1 * NPAD + pc1, c3);
                    }
                }
            }
        }
    }
}

// --------- index prep -------------------------------------------------------
__global__ void tgt_kernel(const int* __restrict__ b2a,
                           const int* __restrict__ b2revb,
                           int* __restrict__ tgt)
{
    int b = blockIdx.x * blockDim.x + threadIdx.x;
    if (b < NB) tgt[b] = b2a[b2revb[b]];
}

__global__ void bucket_kernel(const int* __restrict__ tgt,
                              int* __restrict__ cnt, int* __restrict__ bkt)
{
    int b = blockIdx.x * blockDim.x + threadIdx.x;
    if (b >= NB) return;
    int a = tgt[b];
    int s = atomicAdd(&cnt[a], 1);
    if (s < CAP) bkt[(size_t)a * CAP + s] = b;
}

// --------- gather: out[a] = sum over bucketed bonds of X[b] (permuted space)
__global__ void gather_kernel(const float* __restrict__ X,
                              const int* __restrict__ cnt,
                              const int* __restrict__ bkt,
                              float* __restrict__ out)
{
    const int CH = NPAD / 4; // 80
    int idx = blockIdx.x * blockDim.x + threadIdx.x;
    if (idx >= NA * CH) return;
    int a = idx / CH, c = idx % CH;
    int n = cnt[a]; if (n > CAP) n = CAP;
    const int* bl = bkt + (size_t)a * CAP;
    float4 s = make_float4(0.f, 0.f, 0.f, 0.f);
    for (int j = 0; j < n; j++) {
        float4 v = reinterpret_cast<const float4*>(X + (size_t)bl[j] * NPAD)[c];
        s.x += v.x; s.y += v.y; s.z += v.z; s.w += v.w;
    }
    reinterpret_cast<float4*>(out + (size_t)a * NPAD)[c] = s;
}

// --------- pack A for h0 init (permuted + rounded writes) ------------------
__global__ void pack_h0A(const float* __restrict__ fa, const float* __restrict__ fb,
                         const int* __restrict__ b2a, float* __restrict__ Ain)
{
    size_t idx = (size_t)blockIdx.x * blockDim.x + threadIdx.x;
    if (idx >= (size_t)NB * KP_I) return;
    int r = (int)(idx / KP_I), k = (int)(idx % KP_I);
    float v = 0.f;
    if (k < AF)            v = fa[(size_t)b2a[r] * AF + k];
    else if (k < AF + BFD) v = fb[(size_t)r * BFD + (k - AF)];
    Ain[(size_t)r * KP_I + permcol(k)] = rndtf(v);
}

// --------- pack A for readout (am already permuted; double permutation) ----
__global__ void pack_AoA(const float* __restrict__ fa, const float* __restrict__ am,
                         float* __restrict__ Ain)
{
    size_t idx = (size_t)blockIdx.x * blockDim.x + threadIdx.x;
    if (idx >= (size_t)NA * KP_O) return;
    int a = (int)(idx / KP_O), k = (int)(idx % KP_O);
    float v = 0.f;
    if (k < AF)            v = fa[(size_t)a * AF + k];
    else if (k < AF + HID) v = am[(size_t)a * NPAD + permcol(k - AF)];
    Ain[(size_t)a * KP_O + permcol(k)] = rndtf(v);
}

// --------- zero-pad weight into [320 x KP], permuted k, rounded ------------
__global__ void pad_W(const float* __restrict__ src, int rows, int cols, int KP,
                      float* __restrict__ dst)
{
    int idx = blockIdx.x * blockDim.x + threadIdx.x;
    if (idx >= NPAD * KP) return;
    int rp = idx / KP, k = idx % KP;
    float v = (rp < rows && k < cols) ? src[(size_t)rp * cols + k] : 0.f;
    dst[(size_t)rp * KP + permcol(k)] = rndtf(v);
}

__global__ void pad_bias(const float* __restrict__ src, float* __restrict__ dst)
{
    int c = threadIdx.x + blockIdx.x * blockDim.x;
    if (c < NPAD) dst[c] = (c < HID) ? src[c] : 0.f;   // natural order
}

// --------- round a buffer in place to tf32 (for mol before W_r1 GEMM) ------
__global__ void round_kernel(float* __restrict__ x, int nelem)
{
    int i = blockIdx.x * blockDim.x + threadIdx.x;
    if (i < nelem) x[i] = rndtf(x[i]);
}

// --------- combine: h = relu(h0 + am[b2a] - Y[b2revb]) (permuted space) ----
__global__ void combine_kernel(const float* __restrict__ h0,
                               const float* __restrict__ amsg,
                               const float* __restrict__ Y,
                               const int* __restrict__ b2a,
                               const int* __restrict__ b2revb,
                               float* __restrict__ hout)
{
    const int CH = NPAD / 4; // 80
    size_t tid = (size_t)blockIdx.x * blockDim.x + threadIdx.x;
    if (tid >= (size_t)NB * CH) return;
    int bond = (int)(tid / CH);
    int c = (int)(tid % CH);
    int a  = b2a[bond];
    int rb = b2revb[bond];
    float4 v0 = reinterpret_cast<const float4*>(h0   + (size_t)bond * NPAD)[c];
    float4 va = reinterpret_cast<const float4*>(amsg + (size_t)a    * NPAD)[c];
    float4 vy = reinterpret_cast<const float4*>(Y    + (size_t)rb   * NPAD)[c];
    float4 r;
    r.x = rndtf(fmaxf(v0.x + va.x - vy.x, 0.f));
    r.y = rndtf(fmaxf(v0.y + va.y - vy.y, 0.f));
    r.z = rndtf(fmaxf(v0.z + va.z - vy.z, 0.f));
    r.w = rndtf(fmaxf(v0.w + va.w - vy.w, 0.f));
    reinterpret_cast<float4*>(hout + (size_t)bond * NPAD)[c] = r;
}

// --------- final logits (o1 is permuted; un-permute via invperm) -----------
__global__ void logits_kernel(const float* __restrict__ X,
                              const float* __restrict__ W2,
                              const float* __restrict__ b2,
                              float* __restrict__ out)
{
    int warp = (blockIdx.x * blockDim.x + threadIdx.x) >> 5;
    int lane = threadIdx.x & 31;
    if (warp >= NM) return;
    const float* x = X + (size_t)warp * NPAD;
    float acc[NTASK];
#pragma unroll
    for (int t = 0; t < NTASK; t++) acc[t] = 0.f;
    for (int p = lane; p < NPAD; p += 32) {
        int k = invperm(p);
        if (k >= HID) continue;
        float xv = x[p];
#pragma unroll
        for (int t = 0; t < NTASK; t++)
            acc[t] = fmaf(xv, W2[t * HID + k], acc[t]);
    }
#pragma unroll
    for (int t = 0; t < NTASK; t++) {
        float v = acc[t];
#pragma unroll
        for (int off = 16; off; off >>= 1)
            v += __shfl_down_sync(0xffffffffu, v, off);
        if (lane == 0) out[warp * NTASK + t] = v + b2[t];
    }
}

// ---------------- driver ----------------
extern "C" void kernel_launch(void* const* d_in, const int* in_sizes, int n_in,
                              void* d_out, int out_size)
{
    const float* f_atoms = (const float*)d_in[0];
    const float* f_bonds = (const float*)d_in[1];
    const int*   b2a     = (const int*)d_in[2];
    const int*   b2revb  = (const int*)d_in[3];
    const int*   mol_ids = (const int*)d_in[4];
    const float* W_i     = (const float*)d_in[5];
    const float* W_h     = (const float*)d_in[6];
    const float* W_o     = (const float*)d_in[7];
    const float* b_o     = (const float*)d_in[8];
    const float* W_r1    = (const float*)d_in[9];
    const float* b_r1    = (const float*)d_in[10];
    const float* W_r2    = (const float*)d_in[11];
    const float* b_r2    = (const float*)d_in[12];
    float* out = (float*)d_out;

    float *h0, *h, *Y, *am, *am2, *Ain, *mol, *o1;
    float *WpI, *WpH, *WpO, *WpR, *bO, *bR, *zb;
    int *tgt, *cnt, *bkt;
    cudaGetSymbolAddress((void**)&h0,  g_h0);
    cudaGetSymbolAddress((void**)&h,   g_h);
    cudaGetSymbolAddress((void**)&Y,   g_Y);
    cudaGetSymbolAddress((void**)&am,  g_am);
    cudaGetSymbolAddress((void**)&am2, g_am2);
    cudaGetSymbolAddress((void**)&Ain, g_Ain);
    cudaGetSymbolAddress((void**)&mol, g_mol);
    cudaGetSymbolAddress((void**)&o1,  g_o1);
    cudaGetSymbolAddress((void**)&WpI, g_WpI);
    cudaGetSymbolAddress((void**)&WpH, g_WpH);
    cudaGetSymbolAddress((void**)&WpO, g_WpO);
    cudaGetSymbolAddress((void**)&WpR, g_WpR);
    cudaGetSymbolAddress((void**)&bO,  g_bO);
    cudaGetSymbolAddress((void**)&bR,  g_bR);
    cudaGetSymbolAddress((void**)&zb,  g_zb);
    cudaGetSymbolAddress((void**)&tgt, g_tgt);
    cudaGetSymbolAddress((void**)&cnt, g_cnt);
    cudaGetSymbolAddress((void**)&bkt, g_bkt);

    cudaFuncSetAttribute(mma_gemm<0>, cudaFuncAttributeMaxDynamicSharedMemorySize, SMEM_G);
    cudaFuncSetAttribute(mma_gemm<1>, cudaFuncAttributeMaxDynamicSharedMemorySize, SMEM_G);
    cudaFuncSetAttribute(mma_gemm<2>, cudaFuncAttributeMaxDynamicSharedMemorySize, SMEM_G);

    const dim3 blk(256);
    const dim3 gblk(128);   // GEMM uses 128 threads (4 warps)

    // 0) indices + bucket-CSR + padded weights/biases
    tgt_kernel<<<(NB + 255) / 256, blk>>>(b2a, b2revb, tgt);
    cudaMemsetAsync(cnt, 0, NA * sizeof(int));
    bucket_kernel<<<(NB + 255) / 256, blk>>>(tgt, cnt, bkt);
    pad_W<<<(NPAD * KP_I + 255) / 256, blk>>>(W_i,  HID, AF + BFD, KP_I, WpI);
    pad_W<<<(NPAD * KP_H + 255) / 256, blk>>>(W_h,  HID, HID,      KP_H, WpH);
    pad_W<<<(NPAD * KP_O + 255) / 256, blk>>>(W_o,  HID, AF + HID, KP_O, WpO);
    pad_W<<<(NPAD * KP_H + 255) / 256, blk>>>(W_r1, HID, HID,      KP_H, WpR);
    pad_bias<<<2, 256>>>(b_o,  bO);
    pad_bias<<<2, 256>>>(b_r1, bR);

    // 1) h0 = relu(concat(f_atoms[b2a], f_bonds) @ W_i^T)
    {
        size_t n = (size_t)NB * KP_I;
        pack_h0A<<<(unsigned)((n + 255) / 256), blk>>>(f_atoms, f_bonds, b2a, Ain);
        dim3 g(NT, NB / 128);
        mma_gemm<2><<<g, gblk, SMEM_G>>>(Ain, NB, KP_I, WpI, zb, nullptr, h0, nullptr);
    }

    // 2) DEPTH message rounds:
    //    Y = h @ W_h^T;  am = bucket-gather(Y, tgt);
    //    h' = relu(h0 + am[b2a] - Y[b2revb])   (all in permuted col space)
    const unsigned combB = (unsigned)(((size_t)NB * (NPAD / 4) + 255) / 256);
    const unsigned gatB  = (unsigned)((NA * (NPAD / 4) + 255) / 256);
    float* h_cur = h0;
    for (int d = 0; d < DEPTH; d++) {
        dim3 g(NT, NB / 128);
        mma_gemm<0><<<g, gblk, SMEM_G>>>(h_cur, NB, KP_H, WpH, nullptr, nullptr, Y, nullptr);
        gather_kernel<<<gatB, blk>>>(Y, cnt, bkt, am);
        combine_kernel<<<combB, blk>>>(h0, am, Y, b2a, b2revb, h);
        h_cur = h;
    }

    // 3) final bond->atom aggregation of h via the same buckets
    gather_kernel<<<gatB, blk>>>(h_cur, cnt, bkt, am2);

    // 4) atom readout fused with molecule pooling:
    //    mol += relu(concat(f_atoms, am2) @ W_o^T + b_o) scattered by mol_ids
    {
        size_t n = (size_t)NA * KP_O;
        pack_AoA<<<(unsigned)((n + 255) / 256), blk>>>(f_atoms, am2, Ain);
        cudaMemsetAsync(mol, 0, (size_t)NM * NPAD * sizeof(float));
        dim3 g(NT, (NA + 127) / 128);
        mma_gemm<1><<<g, gblk, SMEM_G>>>(Ain, NA, KP_O, WpO, bO, mol_ids, nullptr, mol);
    }

    // 5) readout head (round mol to tf32 first; its A bits are used raw)
    round_kernel<<<(NM * NPAD + 255) / 256, blk>>>(mol, NM * NPAD);
    {
        dim3 g(NT, (NM + 127) / 128);
        mma_gemm<2><<<g, gblk, SMEM_G>>>(mol, NM, KP_H, WpR, bR, nullptr, o1, nullptr);
    }
    logits_kernel<<<(NM * 32 + 255) / 256, blk>>>(o1, W_r2, b_r2, out);
}